// round 15
// baseline (speedup 1.0000x reference)
#include <cuda_runtime.h>
#include <cuda_fp16.h>
#include <cstdint>

#define D    128
#define HS   128
#define MAXG 16384
#define AP   136      // padded smem row pitch in fp16 elems
#define TILE 32       // rows per tile (5 CTAs per SM)
#define NCTA 740
#define NTHR 128      // 4 warps, no specialization

// ---------------- device scratch ----------------
__device__ float g_den[MAXG];

// ---------------- smem layout (bytes) ----------------
#define SM_BW    0                       // 128 half2 (bias, w) = 512
#define SM_SE    512                     // 2 x 32 f32 = 256
#define SM_BAT   768                     // 32 int = 128
#define SM_BHI   1024                    // 128 x AP fp16 = 34816
#define SM_A0    (SM_BHI + 34816)        // 35840  (32 x AP fp16 = 8704)
#define SMEM1_TOTAL (SM_A0 + 8704)       // 44544  (x5 = 222720 <= 228KB)

// ---------------- helpers ----------------
__device__ __forceinline__ unsigned su32(const void* p) {
    return (unsigned)__cvta_generic_to_shared(p);
}
__device__ __forceinline__ float tanh_approx(float x) {
    float y;
    asm("tanh.approx.f32 %0, %1;" : "=f"(y) : "f"(x));
    return y;
}

#define LDSM4(r0, r1, r2, r3, addr)                                          \
    asm volatile("ldmatrix.sync.aligned.m8n8.x4.shared.b16 {%0,%1,%2,%3}, [%4];" \
                 : "=r"(r0), "=r"(r1), "=r"(r2), "=r"(r3) : "r"(addr))

#define MMA16816F(c, a0, a1, a2, a3, b0, b1)                                 \
    asm volatile(                                                            \
        "mma.sync.aligned.m16n8k16.row.col.f32.f16.f16.f32 "                 \
        "{%0,%1,%2,%3},{%4,%5,%6,%7},{%8,%9},{%0,%1,%2,%3};"                 \
        : "+f"(c[0]), "+f"(c[1]), "+f"(c[2]), "+f"(c[3])                     \
        : "r"(a0), "r"(a1), "r"(a2), "r"(a3), "r"(b0), "r"(b1))

// ---------------- staging: TILE x 128 fp32 -> fp16 (packed cvt) -----------
__device__ __forceinline__ void stage_tile(char* smem, const float* __restrict__ H,
                                           long tile, int V, int tpart) {
    __half* dst = (__half*)(smem + SM_A0);
#pragma unroll
    for (int idx = tpart; idx < TILE * 16; idx += NTHR) {
        int row = idx >> 4;
        int k8  = (idx & 15) << 3;
        long gr = tile * TILE + row;
        float4 v0 = make_float4(0.f, 0.f, 0.f, 0.f), v1 = v0;
        if (gr < (long)V) {
            const float4* p = (const float4*)(H + (size_t)gr * D + k8);
            v0 = p[0];
            v1 = p[1];
        }
        __half2 h0 = __float22half2_rn(make_float2(v0.x, v0.y));
        __half2 h1 = __float22half2_rn(make_float2(v0.z, v0.w));
        __half2 h2 = __float22half2_rn(make_float2(v1.x, v1.y));
        __half2 h3 = __float22half2_rn(make_float2(v1.z, v1.w));
        uint4 pack = make_uint4(*(unsigned*)&h0, *(unsigned*)&h1,
                                *(unsigned*)&h2, *(unsigned*)&h3);
        *(uint4*)(dst + row * AP + k8) = pack;
    }
}

// ---------------- K1: persistent fp16 HMMA + fused softmax-pool -----------
// 5 CTAs per SM: 5 independent MMA streams per SMSP.
__global__ __launch_bounds__(NTHR, 5) void k1_tc(const float* __restrict__ H,
                                                 const void* __restrict__ bt,
                                                 const float* __restrict__ Wp,
                                                 const float* __restrict__ bp,
                                                 const float* __restrict__ ws,
                                                 float* __restrict__ num,
                                                 int V, int nTiles) {
    extern __shared__ __align__(16) char smem[];
    int tid = threadIdx.x, wid = tid >> 5, lane = tid & 31;
    __half2* bw = (__half2*)(smem + SM_BW);   // (bias, w) per col
    float* se   = (float*)(smem + SM_SE);     // [2][32]
    int* sbat   = (int*)(smem + SM_BAT);      // [32]

    bw[tid] = __floats2half2_rn(bp[tid], ws[tid]);
    bool is64 = (((const unsigned long long*)bt)[V / 2 - 1] < (1ULL << 31));

    // stage stationary B = fp16(W) straight from fp32 global
    for (int idx = tid; idx < 128 * 16; idx += NTHR) {
        int row = idx >> 4;
        int k8  = (idx & 15) << 3;
        const float4* p = (const float4*)(Wp + row * D + k8);
        float4 v0 = p[0], v1 = p[1];
        __half2 h0 = __float22half2_rn(make_float2(v0.x, v0.y));
        __half2 h1 = __float22half2_rn(make_float2(v0.z, v0.w));
        __half2 h2 = __float22half2_rn(make_float2(v1.x, v1.y));
        __half2 h3 = __float22half2_rn(make_float2(v1.z, v1.w));
        uint4 pack = make_uint4(*(unsigned*)&h0, *(unsigned*)&h1,
                                *(unsigned*)&h2, *(unsigned*)&h3);
        *(uint4*)((__half*)(smem + SM_BHI) + row * AP + k8) = pack;
    }

    int nt = 0;
    {
        int rem = nTiles - blockIdx.x;
        if (rem > 0) nt = (rem + (int)gridDim.x - 1) / (int)gridDim.x;
    }

    // geometry: 2(M) x 2(N), warp tile 16 x 64 (one m16 subtile per warp)
    int wm = wid >> 1, wn = wid & 1;
    int rb = wm * 16, cb = wn * 64;
    unsigned aoff = ((rb + (lane & 15)) * AP + ((lane >> 4) << 3)) * 2;
    unsigned boff =
        ((cb + (lane & 7) + ((lane >> 4) << 3)) * AP + (((lane >> 3) & 1) << 3)) * 2;
    unsigned bhi_s = su32(smem + SM_BHI) + boff;
    unsigned a_s = su32(smem + SM_A0) + aoff;

    // epilogue constants: packed (b, w) per owned column
    unsigned hw[16];
#pragma unroll
    for (int q = 0; q < 8; ++q)
#pragma unroll
        for (int par = 0; par < 2; ++par) {
            int col = cb + q * 8 + (lane & 3) * 2 + par;
            hw[q * 2 + par] = *(unsigned*)&bw[col];
        }
    __syncthreads();

    for (int j = 0; j < nt; ++j) {
        long tj = (long)blockIdx.x + (long)j * gridDim.x;

        // phase 1: stage A tile + batch ids
        stage_tile((char*)smem, H, tj, V, tid);
        if (tid < TILE) {
            long gr = tj * TILE + tid;
            int g = -1;
            if (gr < (long)V)
                g = is64 ? (int)((const long long*)bt)[gr]
                         : ((const int*)bt)[gr];
            sbat[tid] = g;
        }
        __syncthreads();

        // phase 2: MMA (16 rows x 64 cols per warp)
        float acc[8][4];
#pragma unroll
        for (int q = 0; q < 8; q++)
#pragma unroll
            for (int c = 0; c < 4; c++) acc[q][c] = 0.f;

#pragma unroll
        for (int kk = 0; kk < 8; ++kk) {
            unsigned a0, a1, a2, a3, bh[16];
            LDSM4(a0, a1, a2, a3, a_s + kk * 32);
#pragma unroll
            for (int p = 0; p < 4; ++p)
                LDSM4(bh[4 * p], bh[4 * p + 1], bh[4 * p + 2], bh[4 * p + 3],
                      bhi_s + kk * 32 + p * (16 * AP * 2));
#pragma unroll
            for (int q = 0; q < 8; ++q) {
                int bi = (q >> 1) * 4 + ((q & 1) << 1);
                MMA16816F(acc[q], a0, a1, a2, a3, bh[bi], bh[bi + 1]);
            }
        }

        // phase 3: tanh-dot -> se
        float ps[2] = {0.f, 0.f};
#pragma unroll
        for (int q = 0; q < 8; ++q)
#pragma unroll
            for (int e = 0; e < 4; ++e) {
                __half2 hv = *(__half2*)&hw[q * 2 + (e & 1)];
                float2 bwf = __half22float2(hv);
                float z = acc[q][e] + bwf.x;
                ps[e >> 1] += tanh_approx(z) * bwf.y;
            }
#pragma unroll
        for (int q = 0; q < 2; ++q) {
            ps[q] += __shfl_xor_sync(0xffffffffu, ps[q], 1);
            ps[q] += __shfl_xor_sync(0xffffffffu, ps[q], 2);
        }
        if ((lane & 3) == 0) {
#pragma unroll
            for (int q = 0; q < 2; ++q) {
                int r = rb + (lane >> 2) + q * 8;
                se[wn * 32 + r] = ps[q];
            }
        }
        __syncthreads();

        // phase 4: pooling with inline exp (no max shift: |e| <= ||w||_1 ~ 9).
        // Warp w owns rows [8w, 8w+8); lane owns 4 d-cols.
        {
            const __half* hh = (const __half*)(smem + SM_A0);
            int r0 = wid * 8;
            int d4 = lane * 4;
            float pacc0 = 0.f, pacc1 = 0.f, pacc2 = 0.f, pacc3 = 0.f;
            float psum = 0.f;
            int g = sbat[r0];
#pragma unroll
            for (int rr = 0; rr < 8; ++rr) {
                int r = r0 + rr;
                int gr = sbat[r];
                if (gr != g) {
                    if (g >= 0) {
                        float* dst = num + (size_t)g * D + d4;
                        atomicAdd(dst + 0, pacc0);
                        atomicAdd(dst + 1, pacc1);
                        atomicAdd(dst + 2, pacc2);
                        atomicAdd(dst + 3, pacc3);
                        if (lane == 0) atomicAdd(g_den + g, psum);
                    }
                    pacc0 = pacc1 = pacc2 = pacc3 = 0.f;
                    psum = 0.f;
                    g = gr;
                }
                float p = __expf(se[r] + se[32 + r]);
                uint2 vh = *(const uint2*)(hh + r * AP + d4);
                __half2 h0 = *(__half2*)&vh.x, h1 = *(__half2*)&vh.y;
                float2 f0 = __half22float2(h0), f1 = __half22float2(h1);
                pacc0 += p * f0.x;
                pacc1 += p * f0.y;
                pacc2 += p * f1.x;
                pacc3 += p * f1.y;
                psum += p;
            }
            if (g >= 0) {
                float* dst = num + (size_t)g * D + d4;
                atomicAdd(dst + 0, pacc0);
                atomicAdd(dst + 1, pacc1);
                atomicAdd(dst + 2, pacc2);
                atomicAdd(dst + 3, pacc3);
                if (lane == 0) atomicAdd(g_den + g, psum);
            }
        }
        __syncthreads();
    }
}

// ---------------- K_div: out = num / max(den, 1e-12), 2x float4/thread ----
__global__ void k_div(float4* __restrict__ out, int n4) {
    int i = blockIdx.x * 512 + threadIdx.x;
#pragma unroll
    for (int u = 0; u < 2; ++u, i += 256) {
        if (i < n4) {
            float inv = 1.0f / fmaxf(g_den[i >> 5], 1e-12f);
            float4 v = out[i];
            v.x *= inv; v.y *= inv; v.z *= inv; v.w *= inv;
            out[i] = v;
        }
    }
}

// ---------------- launch ----------------
extern "C" void kernel_launch(void* const* d_in, const int* in_sizes, int n_in,
                              void* d_out, int out_size) {
    const float* H  = (const float*)d_in[0];
    const void*  bt = d_in[1];
    const float* Wp = (const float*)d_in[2];
    const float* bp = (const float*)d_in[3];
    const float* ws = (const float*)d_in[4];
    float* out = (float*)d_out;

    int V = in_sizes[1];
    int nTiles = (V + TILE - 1) / TILE;

    cudaFuncSetAttribute(k1_tc, cudaFuncAttributeMaxDynamicSharedMemorySize,
                         SMEM1_TOTAL);

    // async, graph-capturable zeroing (no allocation)
    cudaMemsetAsync(out, 0, (size_t)out_size * sizeof(float));
    void* denp = nullptr;
    cudaGetSymbolAddress(&denp, g_den);
    cudaMemsetAsync(denp, 0, MAXG * sizeof(float));

    k1_tc<<<NCTA, NTHR, SMEM1_TOTAL>>>(H, bt, Wp, bp, ws, out, V, nTiles);
    int n4 = out_size / 4;
    k_div<<<(n4 + 511) / 512, 256>>>((float4*)out, n4);
}

// round 16
// speedup vs baseline: 1.1575x; 1.1575x over previous
#include <cuda_runtime.h>
#include <cuda_fp16.h>
#include <cstdint>

#define D    128
#define HS   128
#define MAXG 16384
#define AP   136      // padded smem row pitch in fp16 elems
#define TILE 64       // rows per tile (4 CTAs per SM)
#define NCTA 592
#define NTHR 128      // 4 warps, no specialization

// ---------------- device scratch ----------------
__device__ float g_den[MAXG];

// ---------------- smem layout (bytes) ----------------
#define SM_BW    0                       // 128 half2 (bias, w) = 512
#define SM_SE    512                     // 2 x 64 f32 = 512
#define SM_BAT   1024                    // 64 int = 256
#define SM_BHI   1536                    // 128 x AP fp16 = 34816
#define SM_A0    (SM_BHI + 34816)        // 36352  (64 x AP fp16 = 17408)
#define SMEM1_TOTAL (SM_A0 + 17408)      // 53760  (x4 = 215040 <= 228KB)

// ---------------- helpers ----------------
__device__ __forceinline__ unsigned su32(const void* p) {
    return (unsigned)__cvta_generic_to_shared(p);
}
__device__ __forceinline__ float tanh_approx(float x) {
    float y;
    asm("tanh.approx.f32 %0, %1;" : "=f"(y) : "f"(x));
    return y;
}

#define LDSM4(r0, r1, r2, r3, addr)                                          \
    asm volatile("ldmatrix.sync.aligned.m8n8.x4.shared.b16 {%0,%1,%2,%3}, [%4];" \
                 : "=r"(r0), "=r"(r1), "=r"(r2), "=r"(r3) : "r"(addr))

#define MMA16816F(c, a0, a1, a2, a3, b0, b1)                                 \
    asm volatile(                                                            \
        "mma.sync.aligned.m16n8k16.row.col.f32.f16.f16.f32 "                 \
        "{%0,%1,%2,%3},{%4,%5,%6,%7},{%8,%9},{%0,%1,%2,%3};"                 \
        : "+f"(c[0]), "+f"(c[1]), "+f"(c[2]), "+f"(c[3])                     \
        : "r"(a0), "r"(a1), "r"(a2), "r"(a3), "r"(b0), "r"(b1))

// ---------------- staging: TILE x 128 fp32 -> fp16 (packed cvt) -----------
__device__ __forceinline__ void stage_tile(char* smem, const float* __restrict__ H,
                                           long tile, int V, int tpart) {
    __half* dst = (__half*)(smem + SM_A0);
    for (int idx = tpart; idx < TILE * 16; idx += NTHR) {
        int row = idx >> 4;
        int k8  = (idx & 15) << 3;
        long gr = tile * TILE + row;
        float4 v0 = make_float4(0.f, 0.f, 0.f, 0.f), v1 = v0;
        if (gr < (long)V) {
            const float4* p = (const float4*)(H + (size_t)gr * D + k8);
            v0 = p[0];
            v1 = p[1];
        }
        __half2 h0 = __float22half2_rn(make_float2(v0.x, v0.y));
        __half2 h1 = __float22half2_rn(make_float2(v0.z, v0.w));
        __half2 h2 = __float22half2_rn(make_float2(v1.x, v1.y));
        __half2 h3 = __float22half2_rn(make_float2(v1.z, v1.w));
        uint4 pack = make_uint4(*(unsigned*)&h0, *(unsigned*)&h1,
                                *(unsigned*)&h2, *(unsigned*)&h3);
        *(uint4*)(dst + row * AP + k8) = pack;
    }
}

// ---------------- K1: persistent fp16 HMMA + fused softmax-pool -----------
// 4 CTAs per SM; one-time per-slot stagger desynchronizes the co-resident
// CTAs so their serialized stage/epilogue phases interleave with the other
// CTAs' MMA phases instead of convoying.
__global__ __launch_bounds__(NTHR, 4) void k1_tc(const float* __restrict__ H,
                                                 const void* __restrict__ bt,
                                                 const float* __restrict__ Wp,
                                                 const float* __restrict__ bp,
                                                 const float* __restrict__ ws,
                                                 float* __restrict__ num,
                                                 int V, int nTiles) {
    extern __shared__ __align__(16) char smem[];
    int tid = threadIdx.x, wid = tid >> 5, lane = tid & 31;
    __half2* bw = (__half2*)(smem + SM_BW);   // (bias, w) per col
    float* se   = (float*)(smem + SM_SE);     // [2][64]
    int* sbat   = (int*)(smem + SM_BAT);      // [64]

    bw[tid] = __floats2half2_rn(bp[tid], ws[tid]);
    bool is64 = (((const unsigned long long*)bt)[V / 2 - 1] < (1ULL << 31));

    // stage stationary B = fp16(W) straight from fp32 global
    for (int idx = tid; idx < 128 * 16; idx += NTHR) {
        int row = idx >> 4;
        int k8  = (idx & 15) << 3;
        const float4* p = (const float4*)(Wp + row * D + k8);
        float4 v0 = p[0], v1 = p[1];
        __half2 h0 = __float22half2_rn(make_float2(v0.x, v0.y));
        __half2 h1 = __float22half2_rn(make_float2(v0.z, v0.w));
        __half2 h2 = __float22half2_rn(make_float2(v1.x, v1.y));
        __half2 h3 = __float22half2_rn(make_float2(v1.z, v1.w));
        uint4 pack = make_uint4(*(unsigned*)&h0, *(unsigned*)&h1,
                                *(unsigned*)&h2, *(unsigned*)&h3);
        *(uint4*)((__half*)(smem + SM_BHI) + row * AP + k8) = pack;
    }

    int nt = 0;
    {
        int rem = nTiles - blockIdx.x;
        if (rem > 0) nt = (rem + (int)gridDim.x - 1) / (int)gridDim.x;
    }

    // convoy-breaking stagger: co-resident CTAs (same SM, different slot)
    // offset by ~1/4 tile period each. One-time cost <= ~2100 cyc.
    {
        int slot = (blockIdx.x / 148) & 3;
        if (slot) {
            long long lim = (long long)slot * 700;
            long long t0 = clock64();
            while (clock64() - t0 < lim) {}
        }
    }
    __syncthreads();

    // geometry: 2(M) x 2(N), warp tile 32 x 64
    int wm = wid >> 1, wn = wid & 1;
    int rb = wm * 32, cb = wn * 64;
    unsigned aoff = ((rb + (lane & 15)) * AP + ((lane >> 4) << 3)) * 2;
    unsigned boff =
        ((cb + (lane & 7) + ((lane >> 4) << 3)) * AP + (((lane >> 3) & 1) << 3)) * 2;
    unsigned bhi_s = su32(smem + SM_BHI) + boff;
    unsigned a_s = su32(smem + SM_A0) + aoff;

    // epilogue constants: packed (b, w) per owned column
    unsigned hw[16];
#pragma unroll
    for (int q = 0; q < 8; ++q)
#pragma unroll
        for (int par = 0; par < 2; ++par) {
            int col = cb + q * 8 + (lane & 3) * 2 + par;
            hw[q * 2 + par] = *(unsigned*)&bw[col];
        }

    for (int j = 0; j < nt; ++j) {
        long tj = (long)blockIdx.x + (long)j * gridDim.x;

        // phase 1: batch ids first (overlaps with H loads), then stage A tile
        if (tid < TILE) {
            long gr = tj * TILE + tid;
            int g = -1;
            if (gr < (long)V)
                g = is64 ? (int)((const long long*)bt)[gr]
                         : ((const int*)bt)[gr];
            sbat[tid] = g;
        }
        stage_tile((char*)smem, H, tj, V, tid);
        __syncthreads();

        // phase 2: MMA
        float acc[2][8][4];
#pragma unroll
        for (int s = 0; s < 2; s++)
#pragma unroll
            for (int q = 0; q < 8; q++)
#pragma unroll
                for (int c = 0; c < 4; c++) acc[s][q][c] = 0.f;

#pragma unroll
        for (int kk = 0; kk < 8; ++kk) {
            unsigned ah[2][4], bh[16];
#pragma unroll
            for (int s = 0; s < 2; ++s)
                LDSM4(ah[s][0], ah[s][1], ah[s][2], ah[s][3],
                      a_s + kk * 32 + s * (16 * AP * 2));
#pragma unroll
            for (int p = 0; p < 4; ++p)
                LDSM4(bh[4 * p], bh[4 * p + 1], bh[4 * p + 2], bh[4 * p + 3],
                      bhi_s + kk * 32 + p * (16 * AP * 2));
#pragma unroll
            for (int s = 0; s < 2; ++s)
#pragma unroll
                for (int q = 0; q < 8; ++q) {
                    int bi = (q >> 1) * 4 + ((q & 1) << 1);
                    MMA16816F(acc[s][q], ah[s][0], ah[s][1], ah[s][2],
                              ah[s][3], bh[bi], bh[bi + 1]);
                }
        }

        // phase 3: tanh-dot -> se
        float ps[4] = {0.f, 0.f, 0.f, 0.f};
#pragma unroll
        for (int s = 0; s < 2; ++s)
#pragma unroll
            for (int q = 0; q < 8; ++q)
#pragma unroll
                for (int e = 0; e < 4; ++e) {
                    __half2 hv = *(__half2*)&hw[q * 2 + (e & 1)];
                    float2 bwf = __half22float2(hv);
                    float z = acc[s][q][e] + bwf.x;
                    ps[s * 2 + (e >> 1)] += tanh_approx(z) * bwf.y;
                }
#pragma unroll
        for (int q = 0; q < 4; ++q) {
            ps[q] += __shfl_xor_sync(0xffffffffu, ps[q], 1);
            ps[q] += __shfl_xor_sync(0xffffffffu, ps[q], 2);
        }
        if ((lane & 3) == 0) {
#pragma unroll
            for (int q = 0; q < 4; ++q) {
                int r = rb + (q >> 1) * 16 + (lane >> 2) + (q & 1) * 8;
                se[wn * 64 + r] = ps[q];
            }
        }
        __syncthreads();

        // phase 4: pooling with inline exp (no max shift: |e| <= ||w||_1 ~ 9).
        // Warp w owns rows [16w,16w+16); lane owns 4 d-cols.
        {
            const __half* hh = (const __half*)(smem + SM_A0);
            int r0 = wid * 16;
            int d4 = lane * 4;
            float pacc0 = 0.f, pacc1 = 0.f, pacc2 = 0.f, pacc3 = 0.f;
            float psum = 0.f;
            int g = sbat[r0];
#pragma unroll
            for (int rr = 0; rr < 16; ++rr) {
                int r = r0 + rr;
                int gr = sbat[r];
                if (gr != g) {
                    if (g >= 0) {
                        float* dst = num + (size_t)g * D + d4;
                        atomicAdd(dst + 0, pacc0);
                        atomicAdd(dst + 1, pacc1);
                        atomicAdd(dst + 2, pacc2);
                        atomicAdd(dst + 3, pacc3);
                        if (lane == 0) atomicAdd(g_den + g, psum);
                    }
                    pacc0 = pacc1 = pacc2 = pacc3 = 0.f;
                    psum = 0.f;
                    g = gr;
                }
                float p = __expf(se[r] + se[64 + r]);
                uint2 vh = *(const uint2*)(hh + r * AP + d4);
                __half2 h0 = *(__half2*)&vh.x, h1 = *(__half2*)&vh.y;
                float2 f0 = __half22float2(h0), f1 = __half22float2(h1);
                pacc0 += p * f0.x;
                pacc1 += p * f0.y;
                pacc2 += p * f1.x;
                pacc3 += p * f1.y;
                psum += p;
            }
            if (g >= 0) {
                float* dst = num + (size_t)g * D + d4;
                atomicAdd(dst + 0, pacc0);
                atomicAdd(dst + 1, pacc1);
                atomicAdd(dst + 2, pacc2);
                atomicAdd(dst + 3, pacc3);
                if (lane == 0) atomicAdd(g_den + g, psum);
            }
        }
        __syncthreads();
    }
}

// ---------------- K_div: out = num / max(den, 1e-12), 2x float4/thread ----
__global__ void k_div(float4* __restrict__ out, int n4) {
    int i = blockIdx.x * 512 + threadIdx.x;
#pragma unroll
    for (int u = 0; u < 2; ++u, i += 256) {
        if (i < n4) {
            float inv = 1.0f / fmaxf(g_den[i >> 5], 1e-12f);
            float4 v = out[i];
            v.x *= inv; v.y *= inv; v.z *= inv; v.w *= inv;
            out[i] = v;
        }
    }
}

// ---------------- launch ----------------
extern "C" void kernel_launch(void* const* d_in, const int* in_sizes, int n_in,
                              void* d_out, int out_size) {
    const float* H  = (const float*)d_in[0];
    const void*  bt = d_in[1];
    const float* Wp = (const float*)d_in[2];
    const float* bp = (const float*)d_in[3];
    const float* ws = (const float*)d_in[4];
    float* out = (float*)d_out;

    int V = in_sizes[1];
    int nTiles = (V + TILE - 1) / TILE;

    cudaFuncSetAttribute(k1_tc, cudaFuncAttributeMaxDynamicSharedMemorySize,
                         SMEM1_TOTAL);

    // async, graph-capturable zeroing (no allocation)
    cudaMemsetAsync(out, 0, (size_t)out_size * sizeof(float));
    void* denp = nullptr;
    cudaGetSymbolAddress(&denp, g_den);
    cudaMemsetAsync(denp, 0, MAXG * sizeof(float));

    k1_tc<<<NCTA, NTHR, SMEM1_TOTAL>>>(H, bt, Wp, bp, ws, out, V, nTiles);
    int n4 = out_size / 4;
    k_div<<<(n4 + 511) / 512, 256>>>((float4*)out, n4);
}